// round 7
// baseline (speedup 1.0000x reference)
#include <cuda_runtime.h>
#include <cstdint>

// Problem constants
#define B    32
#define H    768
#define W    768
#define IMG  (H * W)               // 589824
#define NPIX (B * IMG)             // 18874368
#define RSM_K 35

// Row chunking: 16 chunks of 48 rows (+18/+17 halo rows read; halo re-reads
// are mostly L2 hits since the whole input fits in L2)
#define CHUNKS 16
#define CHUNK_ROWS (H / CHUNKS)    // 48
#define PAD 20
// Inner extent of a prefix row, padded to multiple of 4 words (805 -> 808)
#define PROW 808

// ---------------------------------------------------------------------------
// Fully fused kernel. 384 threads/block, 2 adjacent columns per thread for the
// vertical state + scan (x0 = 2*tid). Emit phase is specialized: threads
// 0..191 write rsm (4 cols each, STG.128), threads 192..383 write pfm.
// 4 rows per barrier pair.
// ---------------------------------------------------------------------------
__global__ __launch_bounds__(384) void fused_kernel(const float* __restrict__ masks,
                                                    float* __restrict__ out_rsm,
                                                    float* __restrict__ out_pfm) {
    __shared__ __align__(16) uint32_t sPp[4][PROW];  // padded fused prefix, 4 rows
    __shared__ uint32_t sWT[4][12];                  // per-warp totals, 4 rows
    __shared__ uint8_t  sCen[4][384];                // 2 center bits per owner thread

    const int tid   = threadIdx.x;
    const int lane  = tid & 31;
    const int wid   = tid >> 5;                 // 0..11
    const int chunk = blockIdx.x & (CHUNKS - 1);
    const int b     = blockIdx.x >> 4;          // log2(CHUNKS)=4
    const int x0    = tid * 2;
    const int r0    = chunk * CHUNK_ROWS;

    const float* ibase = masks + (size_t)b * IMG + x0;

    // Left pad zeros (first read happens after two later barriers)
    if (tid < PAD) {
        sPp[0][tid] = 0; sPp[1][tid] = 0; sPp[2][tid] = 0; sPp[3][tid] = 0;
    }

    uint64_t win0 = 0, win1 = 0;

    // ---- Prologue: shift in rows r0-18 .. r0+16 (35 rows), batches of 7 ----
    #pragma unroll 1
    for (int pb = 0; pb < 35; pb += 7) {
        float2 f[7];
        #pragma unroll
        for (int i = 0; i < 7; ++i) {
            const int t = r0 - 18 + pb + i;     // t <= 736 < H always
            f[i] = make_float2(0.f, 0.f);
            if (t >= 0) f[i] = *(const float2*)(ibase + (size_t)t * W);
        }
        #pragma unroll
        for (int i = 0; i < 7; ++i) {
            win0 = (win0 << 1) | (uint64_t)(f[i].x > 0.5f);
            win1 = (win1 << 1) | (uint64_t)(f[i].y > 0.5f);
        }
    }

    // Seed fused v at y = r0-1: cnt35 = popc bits 0..34 ; cnt31 = popc bits 2..32
    const uint64_t M35 = (1ULL << 35) - 1;
    const uint64_t M31 = (1ULL << 31) - 1;
    uint32_t v0 = ((uint32_t)__popcll(win0 & M35) << 16) |
                   (uint32_t)__popcll((win0 >> 2) & M31);
    uint32_t v1 = ((uint32_t)__popcll(win1 & M35) << 16) |
                   (uint32_t)__popcll((win1 >> 2) & M31);

    const float inv = 1.0f / (float)(RSM_K * RSM_K);

    // ---- Main loop: 4 rows per load batch and per barrier pair ----
    #pragma unroll 1
    for (int yb = 0; yb < CHUNK_ROWS; yb += 4) {
        float2 f[4];
        #pragma unroll
        for (int i = 0; i < 4; ++i) {
            const int t = r0 + yb + i + 17;
            f[i] = make_float2(0.f, 0.f);
            if (t < H) f[i] = *(const float2*)(ibase + (size_t)t * W);
        }

        // Vertical updates for 4 rows; snapshot fused values
        uint32_t va[4][2];
        uint32_t cenpack = 0;                    // bit (i*2+c) = center bit
        #pragma unroll
        for (int i = 0; i < 4; ++i) {
            const uint32_t m0 = (f[i].x > 0.5f);
            const uint32_t m1 = (f[i].y > 0.5f);

            win0 = (win0 << 1) | (uint64_t)m0;
            {
                const uint32_t lo = (uint32_t)win0;
                const uint32_t hi = (uint32_t)(win0 >> 32);
                v0 += (m0 - ((hi >> 3) & 1u)) * 65536u
                    + (((lo >> 2) & 1u) - ((hi >> 1) & 1u));
                cenpack |= ((lo >> 17) & 1u) << (i * 2);
            }
            va[i][0] = v0;

            win1 = (win1 << 1) | (uint64_t)m1;
            {
                const uint32_t lo = (uint32_t)win1;
                const uint32_t hi = (uint32_t)(win1 >> 32);
                v1 += (m1 - ((hi >> 3) & 1u)) * 65536u
                    + (((lo >> 2) & 1u) - ((hi >> 1) & 1u));
                cenpack |= ((lo >> 17) & 1u) << (i * 2 + 1);
            }
            va[i][1] = v1;
        }

        // 4 independent warp scans (ILP), then one barrier
        uint32_t pr1[4], pr0[4], sc[4];
        #pragma unroll
        for (int i = 0; i < 4; ++i) {
            pr0[i] = va[i][0];
            pr1[i] = pr0[i] + va[i][1];
            uint32_t x = pr1[i];
            #pragma unroll
            for (int d = 1; d < 32; d <<= 1) {
                uint32_t y = __shfl_up_sync(0xFFFFFFFFu, x, d);
                if (lane >= d) x += y;
            }
            sc[i] = x;
            if (lane == 31) sWT[i][wid] = x;
        }
        __syncthreads();

        #pragma unroll
        for (int i = 0; i < 4; ++i) {
            // Redundant 12-element cross-warp scan in every warp
            uint32_t tw = (lane < 12) ? sWT[i][lane] : 0u;
            #pragma unroll
            for (int d = 1; d < 16; d <<= 1) {
                uint32_t y = __shfl_up_sync(0xFFFFFFFFu, tw, d);
                if (lane >= d) tw += y;
            }
            const uint32_t tot = __shfl_sync(0xFFFFFFFFu, tw, 11);
            const uint32_t exw = __shfl_sync(0xFFFFFFFFu, tw, (wid > 0) ? (wid - 1) : 0);
            const uint32_t excl = (sc[i] - pr1[i]) + ((wid > 0) ? exw : 0u);

            uint2 q;
            q.x = excl + pr0[i];
            q.y = excl + pr1[i];
            *(uint2*)&sPp[i][PAD + x0] = q;
            if (tid < 17) sPp[i][PAD + W + tid] = tot;   // right pad = row total
            // Center bits for this owner's 2 columns (written here, between the
            // barriers, so previous group's emitters are done reading sCen)
            sCen[i][tid] = (uint8_t)((cenpack >> (i * 2)) & 3u);
        }
        __syncthreads();

        // ---- Specialized emit: half rsm, half pfm; 4 cols each, STG.128 ----
        if (tid < 192) {
            const int xe = tid * 4;
            float* obase = out_rsm + (size_t)b * IMG + (size_t)(r0 + yb) * W + xe;
            #pragma unroll
            for (int i = 0; i < 4; ++i) {
                // lo35_j = P[x-18+PAD] = sPp[xe+2+j] ; h35_j = sPp[xe+37+j]
                const uint2 lo35a = *(const uint2*)&sPp[i][xe + 2];
                const uint2 lo35b = *(const uint2*)&sPp[i][xe + 4];
                const uint32_t h0 = sPp[i][xe + 37];
                const uint2 hab   = *(const uint2*)&sPp[i][xe + 38];
                const uint32_t h3 = sPp[i][xe + 40];

                float4 r4;
                r4.x = (float)((h0    - lo35a.x) >> 16) * inv;
                r4.y = (float)((hab.x - lo35a.y) >> 16) * inv;
                r4.z = (float)((hab.y - lo35b.x) >> 16) * inv;
                r4.w = (float)((h3    - lo35b.y) >> 16) * inv;
                *(float4*)(obase + (size_t)i * W) = r4;
            }
        } else {
            const int e  = tid - 192;
            const int xe = e * 4;
            float* obase = out_pfm + (size_t)b * IMG + (size_t)(r0 + yb) * W + xe;
            #pragma unroll
            for (int i = 0; i < 4; ++i) {
                // lo31_j = P[x-16+PAD] = sPp[xe+4+j] ; h31_j = sPp[xe+35+j]
                const uint4 lo31 = *(const uint4*)&sPp[i][xe + 4];
                const uint32_t g0 = sPp[i][xe + 35];
                const uint2 gab   = *(const uint2*)&sPp[i][xe + 36];
                const uint32_t g3 = sPp[i][xe + 38];

                const uint32_t cw = *(const uint16_t*)&sCen[i][e * 2];
                // byte0 bit0 = col xe, bit1 = col xe+1; byte1 bit0 = xe+2, bit1 = xe+3
                const uint32_t f31_0 = (g0    - lo31.x) & 0xFFFFu;
                const uint32_t f31_1 = (gab.x - lo31.y) & 0xFFFFu;
                const uint32_t f31_2 = (gab.y - lo31.z) & 0xFFFFu;
                const uint32_t f31_3 = (g3    - lo31.w) & 0xFFFFu;

                float4 p4;
                p4.x = (float)((cw & 1u)        + ((f31_0 == 0u) ? 2u : 0u));
                p4.y = (float)(((cw >> 1) & 1u) + ((f31_1 == 0u) ? 2u : 0u));
                p4.z = (float)(((cw >> 8) & 1u) + ((f31_2 == 0u) ? 2u : 0u));
                p4.w = (float)(((cw >> 9) & 1u) + ((f31_3 == 0u) ? 2u : 0u));
                *(float4*)(obase + (size_t)i * W) = p4;
            }
        }
    }
}

// ---------------------------------------------------------------------------
extern "C" void kernel_launch(void* const* d_in, const int* in_sizes, int n_in,
                              void* d_out, int out_size) {
    const float* masks = (const float*)d_in[0];
    float* out = (float*)d_out;

    fused_kernel<<<B * CHUNKS, 384>>>(masks, out, out + NPIX);
}

// round 8
// speedup vs baseline: 1.1734x; 1.1734x over previous
#include <cuda_runtime.h>
#include <cstdint>

// Problem constants
#define B    32
#define H    768
#define W    768
#define IMG  (H * W)               // 589824
#define NPIX (B * IMG)             // 18874368
#define RSM_K 35

// Pass-1 row chunking: 12 chunks of 64 rows (+17/+16 halo)
#define CHUNKS 12
#define CHUNK_ROWS (H / CHUNKS)    // 64

// Intermediate: one byte per pixel.
//   bits 0-5 : vertical 35-window popcount (0..35)
//   bit  6   : center mask bit
//   bit  7   : vertical 31-window "any" flag
__device__ uint8_t g_packed[NPIX];

// ---------------------------------------------------------------------------
// Pass 1: vertical sliding bit-window. Thread owns 4 adjacent columns
// (float4 loads, one packed STG.32 per row). grid: B*CHUNKS blocks of 192.
// ---------------------------------------------------------------------------
__global__ __launch_bounds__(192) void pass1_vertical(const float* __restrict__ masks) {
    const int tid   = threadIdx.x;
    const int chunk = blockIdx.x % CHUNKS;
    const int b     = blockIdx.x / CHUNKS;
    const int x0    = tid * 4;
    const int r0    = chunk * CHUNK_ROWS;

    const float* ibase = masks + (size_t)b * IMG + x0;
    uint8_t*     obase = g_packed + (size_t)b * IMG + x0;

    const uint64_t M35 = (1ULL << 35) - 1;
    const uint64_t M31 = (1ULL << 31) - 1;

    uint64_t win[4] = {0, 0, 0, 0};

    // Prologue: rows r0-17 .. r0+16 (34 rows), two batches of 17 loads
    #pragma unroll 1
    for (int pb = 0; pb < 34; pb += 17) {
        float4 f[17];
        #pragma unroll
        for (int i = 0; i < 17; ++i) {
            const int t = r0 - 17 + pb + i;     // t <= r0+16 <= 720 < H
            f[i] = make_float4(0.f, 0.f, 0.f, 0.f);
            if (t >= 0) f[i] = *(const float4*)(ibase + (size_t)t * W);
        }
        #pragma unroll
        for (int i = 0; i < 17; ++i) {
            win[0] = (win[0] << 1) | (uint64_t)(f[i].x > 0.5f);
            win[1] = (win[1] << 1) | (uint64_t)(f[i].y > 0.5f);
            win[2] = (win[2] << 1) | (uint64_t)(f[i].z > 0.5f);
            win[3] = (win[3] << 1) | (uint64_t)(f[i].w > 0.5f);
        }
    }

    // Emit loop: batches of 8 rows (8 LDG.128 in flight per warp)
    #pragma unroll 1
    for (int yb = 0; yb < CHUNK_ROWS; yb += 8) {
        float4 f[8];
        #pragma unroll
        for (int i = 0; i < 8; ++i) {
            const int t = r0 + yb + i + 17;
            f[i] = make_float4(0.f, 0.f, 0.f, 0.f);
            if (t < H) f[i] = *(const float4*)(ibase + (size_t)t * W);
        }
        #pragma unroll
        for (int i = 0; i < 8; ++i) {
            win[0] = (win[0] << 1) | (uint64_t)(f[i].x > 0.5f);
            win[1] = (win[1] << 1) | (uint64_t)(f[i].y > 0.5f);
            win[2] = (win[2] << 1) | (uint64_t)(f[i].z > 0.5f);
            win[3] = (win[3] << 1) | (uint64_t)(f[i].w > 0.5f);

            uint32_t pack = 0;
            #pragma unroll
            for (int c = 0; c < 4; ++c) {
                const uint32_t cnt    = (uint32_t)__popcll(win[c] & M35);
                const uint32_t center = (uint32_t)((win[c] >> 17) & 1ULL);
                const uint32_t flag   = (((win[c] >> 2) & M31) != 0ULL) ? 1u : 0u;
                pack |= (cnt | (center << 6) | (flag << 7)) << (c * 8);
            }
            const int y = r0 + yb + i;
            *(uint32_t*)(obase + (size_t)y * W) = pack;
        }
    }
}

// ---------------------------------------------------------------------------
// Pass 2: warp-autonomous horizontal sliding window. One warp per row,
// 25 tiles of 32 columns (tile 24 is a zero drain tile that makes the prefix
// saturate at the row total, providing the right-edge clamp for free).
// No shared memory, no __syncthreads.
//
// Inclusive prefix p[x] of v = (cnt35 << 16) | flag. For output xo:
//   rsm: p[min(xo+17,W-1)] - p[xo-18]   (hi in cur tile: own lane)
//   pfm: p[min(xo+15,W-1)] - p[xo-16]
// Edges taken from cur/prev/prev2 tile prefixes via shuffles.
// ---------------------------------------------------------------------------
__global__ __launch_bounds__(256) void pass2_horizontal(float* __restrict__ out_rsm,
                                                        float* __restrict__ out_pfm) {
    const int lane = threadIdx.x & 31;
    const int wid  = threadIdx.x >> 5;
    const int row  = blockIdx.x * 8 + wid;      // b*H + y

    const uint8_t* rowbase = g_packed + (size_t)row * W;
    float* rsm_row = out_rsm + (size_t)row * W;
    float* pfm_row = out_pfm + (size_t)row * W;

    const float inv = 1.0f / (float)(RSM_K * RSM_K);

    uint32_t carry   = 0;
    uint32_t prev_p  = 0, prev2_p = 0;
    uint32_t b_prev  = 0;

    const int i29 = (lane + 29) & 31;   // lane-3  (or lane+29)
    const int i30 = (lane + 30) & 31;   // lane-2  (or lane+30)
    const int i31 = (lane + 31) & 31;   // lane-1  (or lane+31)
    const int i15 = (lane + 15) & 31;   // lane-17 (or lane+15)

    #pragma unroll 5
    for (int t = 0; t < 25; ++t) {
        // Load this tile's packed byte (zero for the drain tile)
        uint32_t b_cur = 0;
        if (t < 24) b_cur = rowbase[t * 32 + lane];
        uint32_t v = ((b_cur & 63u) << 16) | (b_cur >> 7);

        // Warp inclusive scan
        uint32_t x = v;
        #pragma unroll
        for (int d = 1; d < 32; d <<= 1) {
            uint32_t y = __shfl_up_sync(0xFFFFFFFFu, x, d);
            if (lane >= d) x += y;
        }
        const uint32_t p_cur = carry + x;
        carry = __shfl_sync(0xFFFFFFFFu, p_cur, 31);

        // Window edges for xo = 32t - 17 + lane
        const uint32_t hi35 = p_cur;                                   // p[32t+lane]
        const uint32_t s1 = __shfl_sync(0xFFFFFFFFu, prev_p,  i29);
        const uint32_t s2 = __shfl_sync(0xFFFFFFFFu, prev2_p, i29);
        const uint32_t lo35 = (lane >= 3) ? s1 : s2;                   // p[xo-18]

        const uint32_t a1 = __shfl_sync(0xFFFFFFFFu, p_cur,  i30);
        const uint32_t a2 = __shfl_sync(0xFFFFFFFFu, prev_p, i30);
        const uint32_t hi31 = (lane >= 2) ? a1 : a2;                   // p[xo+15]

        const uint32_t c1 = __shfl_sync(0xFFFFFFFFu, prev_p,  i31);
        const uint32_t c2 = __shfl_sync(0xFFFFFFFFu, prev2_p, i31);
        const uint32_t lo31 = (lane >= 1) ? c1 : c2;                   // p[xo-16]

        const uint32_t e1 = __shfl_sync(0xFFFFFFFFu, b_cur,  i15);
        const uint32_t e2 = __shfl_sync(0xFFFFFFFFu, b_prev, i15);
        const uint32_t eb = (lane >= 17) ? e1 : e2;                    // byte at xo
        const uint32_t cen = (eb >> 6) & 1u;

        const int xo = t * 32 - 17 + lane;
        if (xo >= 0 && xo < W) {
            // hi - lo: no cross-field borrow (both fields monotone)
            const uint32_t d35 = (hi35 - lo35) >> 16;
            const uint32_t f31 = (hi31 - lo31) & 0xFFFFu;
            rsm_row[xo] = (float)d35 * inv;
            // pfm = center ? 1 : (any31 ? 0 : 2) == center + 2*(f31==0)
            pfm_row[xo] = (float)(cen + ((f31 == 0u) ? 2u : 0u));
        }

        prev2_p = prev_p;
        prev_p  = p_cur;
        b_prev  = b_cur;
    }
}

// ---------------------------------------------------------------------------
extern "C" void kernel_launch(void* const* d_in, const int* in_sizes, int n_in,
                              void* d_out, int out_size) {
    const float* masks = (const float*)d_in[0];
    float* out = (float*)d_out;

    pass1_vertical<<<B * CHUNKS, 192>>>(masks);
    pass2_horizontal<<<B * H / 8, 256>>>(out, out + NPIX);
}

// round 9
// speedup vs baseline: 1.4671x; 1.2502x over previous
#include <cuda_runtime.h>
#include <cstdint>

// Problem constants
#define B    32
#define H    768
#define W    768
#define IMG  (H * W)               // 589824
#define NPIX (B * IMG)             // 18874368
#define RSM_K 35

// Pass-1 row chunking: 16 chunks of 48 rows (+17/+16 halo)
#define CHUNKS 16
#define CHUNK_ROWS (H / CHUNKS)    // 48

// Intermediate: one byte per pixel.
//   bits 0-5 : vertical 35-window popcount (0..35)
//   bit  6   : center mask bit
//   bit  7   : vertical 31-window "any" flag
__device__ uint8_t g_packed[NPIX];

// ---------------------------------------------------------------------------
// Pass 1: vertical sliding bit-window. Thread owns 2 adjacent columns
// (float2 loads, one packed uint16 store per row).
// grid: B*CHUNKS = 512 blocks of 384 threads (full row width).
// ---------------------------------------------------------------------------
__global__ __launch_bounds__(384) void pass1_vertical(const float* __restrict__ masks) {
    const int tid   = threadIdx.x;
    const int chunk = blockIdx.x & (CHUNKS - 1);
    const int b     = blockIdx.x >> 4;          // log2(CHUNKS)=4
    const int x0    = tid * 2;
    const int r0    = chunk * CHUNK_ROWS;

    const float* ibase = masks + (size_t)b * IMG + x0;
    uint8_t*     obase = g_packed + (size_t)b * IMG + x0;

    const uint64_t M35 = (1ULL << 35) - 1;
    const uint64_t M31 = (1ULL << 31) - 1;

    uint64_t win0 = 0, win1 = 0;

    // Prologue: rows r0-17 .. r0+16 (34 rows), two batches of 17 loads
    #pragma unroll 1
    for (int pb = 0; pb < 34; pb += 17) {
        float2 f[17];
        #pragma unroll
        for (int i = 0; i < 17; ++i) {
            const int t = r0 - 17 + pb + i;     // t <= r0+16 <= 736 < H
            f[i] = make_float2(0.f, 0.f);
            if (t >= 0) f[i] = *(const float2*)(ibase + (size_t)t * W);
        }
        #pragma unroll
        for (int i = 0; i < 17; ++i) {
            win0 = (win0 << 1) | (uint64_t)(f[i].x > 0.5f);
            win1 = (win1 << 1) | (uint64_t)(f[i].y > 0.5f);
        }
    }

    // Emit loop: batches of 8 rows (8 LDG.64 in flight per warp)
    #pragma unroll 1
    for (int yb = 0; yb < CHUNK_ROWS; yb += 8) {
        float2 f[8];
        #pragma unroll
        for (int i = 0; i < 8; ++i) {
            const int t = r0 + yb + i + 17;
            f[i] = make_float2(0.f, 0.f);
            if (t < H) f[i] = *(const float2*)(ibase + (size_t)t * W);
        }
        #pragma unroll
        for (int i = 0; i < 8; ++i) {
            win0 = (win0 << 1) | (uint64_t)(f[i].x > 0.5f);
            win1 = (win1 << 1) | (uint64_t)(f[i].y > 0.5f);

            const uint32_t p0 = (uint32_t)__popcll(win0 & M35)
                              | ((uint32_t)((win0 >> 17) & 1ULL) << 6)
                              | ((((win0 >> 2) & M31) != 0ULL) ? 0x80u : 0u);
            const uint32_t p1 = (uint32_t)__popcll(win1 & M35)
                              | ((uint32_t)((win1 >> 17) & 1ULL) << 6)
                              | ((((win1 >> 2) & M31) != 0ULL) ? 0x80u : 0u);

            const int y = r0 + yb + i;
            *(uint16_t*)(obase + (size_t)y * W) = (uint16_t)(p0 | (p1 << 8));
        }
    }
}

// ---------------------------------------------------------------------------
// Pass 2: per-row horizontal windows via one fused prefix sum.
// 192 threads per block, one row per block, 4 outputs per thread.
// Prefix array padded: [0..19] zeros, [20..20+W) prefix, [20+W..20+W+16] total.
// (Measured-best variant from R3.)
// ---------------------------------------------------------------------------
#define PAD 20

__global__ __launch_bounds__(192) void pass2_horizontal(float* __restrict__ out_rsm,
                                                        float* __restrict__ out_pfm) {
    __shared__ __align__(16) uint32_t sPp[PAD + W + 17];  // padded fused prefix
    __shared__ uint32_t sWarp[6];

    const int tid  = threadIdx.x;
    const int lane = tid & 31;
    const int wid  = tid >> 5;
    const int row  = blockIdx.x;        // b*H + y
    const int x0   = tid * 4;

    // One u32 = this thread's 4 packed bytes (byte j -> x = x0 + j)
    const uint32_t w = ((const uint32_t*)(g_packed + (size_t)row * W))[tid];

    if (tid < PAD) sPp[tid] = 0;

    // Unpack: v = (cnt << 16) | flag
    uint32_t v0, v1, v2, v3;
    {
        uint32_t c0 = (w      ) & 63u, f0 = (w >> 7 ) & 1u;
        uint32_t c1 = (w >> 8 ) & 63u, f1 = (w >> 15) & 1u;
        uint32_t c2 = (w >> 16) & 63u, f2 = (w >> 23) & 1u;
        uint32_t c3 = (w >> 24) & 63u, f3 = (w >> 31);
        v0 = c0 * 65536u + f0;
        v1 = c1 * 65536u + f1;
        v2 = c2 * 65536u + f2;
        v3 = c3 * 65536u + f3;
    }
    const uint32_t s0 = v0;
    const uint32_t s1 = s0 + v1;
    const uint32_t s2 = s1 + v2;
    const uint32_t s3 = s2 + v3;

    // Warp inclusive scan of per-thread totals
    uint32_t sc = s3;
    #pragma unroll
    for (int d = 1; d < 32; d <<= 1) {
        uint32_t y = __shfl_up_sync(0xFFFFFFFFu, sc, d);
        if (lane >= d) sc += y;
    }
    if (lane == 31) sWarp[wid] = sc;
    __syncthreads();
    if (tid == 0) {
        uint32_t acc = sWarp[0];
        #pragma unroll
        for (int i = 1; i < 6; ++i) { acc += sWarp[i]; sWarp[i] = acc; }
    }
    __syncthreads();

    const uint32_t excl = (sc - s3) + (wid ? sWarp[wid - 1] : 0u);

    // Inclusive prefix at x0..x0+3 (vector STS)
    {
        uint4 p;
        p.x = excl + s0;
        p.y = excl + s1;
        p.z = excl + s2;
        p.w = excl + s3;
        *(uint4*)&sPp[PAD + x0] = p;
    }
    // Right pad: replicate row total P[W-1]
    if (tid < 17) sPp[PAD + W + tid] = sWarp[5];
    __syncthreads();

    // Window reads (all indices pre-shifted by PAD=20):
    //   lo35_j = sPp[x0 + j + 2]   (x - 18 + PAD)
    //   lo31_j = sPp[x0 + j + 4]   (x - 16 + PAD)
    //   hi31_j = sPp[x0 + j + 35]  (x + 15 + PAD, clamp via right pad)
    //   hi35_j = sPp[x0 + j + 37]  (x + 17 + PAD, clamp via right pad)
    const uint2 A01 = *(const uint2*)&sPp[x0 + 2];   // [x0+2, x0+3]
    const uint4 A25 = *(const uint4*)&sPp[x0 + 4];   // [x0+4 .. x0+7]
    const uint32_t b35 = sPp[x0 + 35];
    const uint4 B69 = *(const uint4*)&sPp[x0 + 36];  // [x0+36 .. x0+39]
    const uint32_t b40 = sPp[x0 + 40];

    const float inv = 1.0f / (float)(RSM_K * RSM_K);

    // hi - lo has no cross-field borrow (both fields monotone):
    //   sum35 = (hi35 - lo35) >> 16,  f31 = (hi31 - lo31) & 0xFFFF
    uint32_t d35_0 = B69.y - A01.x;
    uint32_t d35_1 = B69.z - A01.y;
    uint32_t d35_2 = B69.w - A25.x;
    uint32_t d35_3 = b40   - A25.y;

    uint32_t f31_0 = (b35   - A25.x) & 0xFFFFu;
    uint32_t f31_1 = (B69.x - A25.y) & 0xFFFFu;
    uint32_t f31_2 = (B69.y - A25.z) & 0xFFFFu;
    uint32_t f31_3 = (B69.z - A25.w) & 0xFFFFu;

    float4 rsm4;
    rsm4.x = (float)(d35_0 >> 16) * inv;
    rsm4.y = (float)(d35_1 >> 16) * inv;
    rsm4.z = (float)(d35_2 >> 16) * inv;
    rsm4.w = (float)(d35_3 >> 16) * inv;

    // pfm = center ? 1 : (f31 ? 0 : 2) == center + 2*(f31==0)
    float4 pfm4;
    pfm4.x = (float)(((w >> 6)  & 1u) + ((f31_0 == 0u) ? 2u : 0u));
    pfm4.y = (float)(((w >> 14) & 1u) + ((f31_1 == 0u) ? 2u : 0u));
    pfm4.z = (float)(((w >> 22) & 1u) + ((f31_2 == 0u) ? 2u : 0u));
    pfm4.w = (float)(((w >> 30) & 1u) + ((f31_3 == 0u) ? 2u : 0u));

    *(float4*)(out_rsm + (size_t)row * W + x0) = rsm4;
    *(float4*)(out_pfm + (size_t)row * W + x0) = pfm4;
}

// ---------------------------------------------------------------------------
extern "C" void kernel_launch(void* const* d_in, const int* in_sizes, int n_in,
                              void* d_out, int out_size) {
    const float* masks = (const float*)d_in[0];
    float* out = (float*)d_out;

    pass1_vertical<<<B * CHUNKS, 384>>>(masks);
    pass2_horizontal<<<B * H, 192>>>(out, out + NPIX);
}